// round 7
// baseline (speedup 1.0000x reference)
#include <cuda_runtime.h>
#include <cstdint>

// BatchDelayProcessor: lag-D feedback delay line.
//   c_k = x_k + FB * c_{k-1}         (carry per chain, c_{-1} = 0)
//   out_k = (1-MIX) * x_k + MIX * c_{k-1}
//
// R6: all cache-hint / schedule variants were neutral (steady state = 226MB
// per replay @ ~5.7TB/s). Remaining untested lever: 128-bit global accesses.
// The k-block stride (88200B = 8 mod 16) forbids direct float4 per chain, so
// stage each 4KB region through shared memory with float4 cooperative copies
// (float2 at the misaligned edges), compute from smem, store back the same way.

#define D_SAMP   22050
#define T_LEN    441000
#define B_SZ     64
#define NBLK     20
#define FB       0.3f
#define MIXC     0.5f

#define TILE           1024                        // floats per CTA tile
#define TILES_PER_ROW  22                          // ceil(22050/1024)
#define LAST_LEN       (D_SAMP - (TILES_PER_ROW-1)*TILE)   // 546

__global__ __launch_bounds__(256) void delay_kernel(const float* __restrict__ x,
                                                    float* __restrict__ out) {
    __shared__ __align__(16) float sin_[TILE + 4];
    __shared__ __align__(16) float sout_[TILE + 4];

    const int tid  = threadIdx.x;
    const int tile = blockIdx.x % TILES_PER_ROW;
    const int b    = blockIdx.x / TILES_PER_ROW;
    const int j0   = tile * TILE;
    const int len  = (tile == TILES_PER_ROW - 1) ? LAST_LEN : TILE;
    const int lenB = len * 4;

    const char* xrow = (const char*)(x + (size_t)b * T_LEN) + (size_t)j0 * 4;
    char*       orow = (char*)(out + (size_t)b * T_LEN) + (size_t)j0 * 4;

    const int e = tid * 4;                 // this thread's first chain in tile
    float c0 = 0.f, c1 = 0.f, c2 = 0.f, c3 = 0.f;

#pragma unroll 1
    for (int k = 0; k < NBLK; k++) {
        const size_t goff = (size_t)k * (size_t)(D_SAMP * 4);   // k*88200
        const char* g = xrow + goff;
        char*       o = orow + goff;
        const int al = (8 * k) & 15;       // region start alignment: 0 or 8
        const int q0 = (16 - al) & 15;     // bytes to first 16B-aligned point
        char* sB  = (char*)sin_;
        char* soB = (char*)sout_;

        // ---- cooperative load: global [0,lenB) -> smem bytes [al, al+lenB)
        if (q0 && tid == 0)
            *(float2*)(sB + al) = *(const float2*)(g);
        const int n4 = (lenB - q0) >> 4;
        for (int i = tid; i < n4; i += 256)
            *(float4*)(sB + al + q0 + 16 * i) = *(const float4*)(g + q0 + 16 * i);
        const int done = q0 + 16 * n4;
        if ((lenB - done) == 8 && tid == 0)
            *(float2*)(sB + al + done) = *(const float2*)(g + done);
        __syncthreads();

        // ---- compute: element i lives at smem byte al + 4*i
        if (e + 3 < len) {
            const float2* si = (const float2*)(sB + al + 4 * e);
            float2*       so = (float2*)(soB + al + 4 * e);
            float2 a = si[0], bv = si[1];
            float2 oa, ob;
            oa.x = fmaf(c0, MIXC, a.x * (1.0f - MIXC));
            oa.y = fmaf(c1, MIXC, a.y * (1.0f - MIXC));
            ob.x = fmaf(c2, MIXC, bv.x * (1.0f - MIXC));
            ob.y = fmaf(c3, MIXC, bv.y * (1.0f - MIXC));
            so[0] = oa; so[1] = ob;
            c0 = fmaf(c0, FB, a.x);
            c1 = fmaf(c1, FB, a.y);
            c2 = fmaf(c2, FB, bv.x);
            c3 = fmaf(c3, FB, bv.y);
        } else if (e < len) {
            // partial-tile stragglers: scalar with per-element guards
            const float* sif = (const float*)(sB + al);
            float*       sof = (float*)(soB + al);
            float* cc[4] = {&c0, &c1, &c2, &c3};
#pragma unroll
            for (int q = 0; q < 4; q++) {
                if (e + q < len) {
                    float xv = sif[e + q];
                    sof[e + q] = fmaf(*cc[q], MIXC, xv * (1.0f - MIXC));
                    *cc[q] = fmaf(*cc[q], FB, xv);
                }
            }
        }
        __syncthreads();

        // ---- cooperative store: smem bytes [al, al+lenB) -> global [0,lenB)
        if (q0 && tid == 0)
            *(float2*)(o) = *(const float2*)(soB + al);
        for (int i = tid; i < n4; i += 256)
            *(float4*)(o + q0 + 16 * i) = *(const float4*)(soB + al + q0 + 16 * i);
        if ((lenB - done) == 8 && tid == 0)
            *(float2*)(o + done) = *(const float2*)(soB + al + done);
        // no barrier needed here: next load writes sin_ (not sout_), and the
        // next compute phase (which overwrites sout_) is fenced by the next
        // post-load __syncthreads().
    }
}

extern "C" void kernel_launch(void* const* d_in, const int* in_sizes, int n_in,
                              void* d_out, int out_size) {
    const float* x = (const float*)d_in[0];
    float* out = (float*)d_out;

    const int blocks = B_SZ * TILES_PER_ROW;   // 1408
    delay_kernel<<<blocks, 256>>>(x, out);
}

// round 8
// speedup vs baseline: 1.4649x; 1.4649x over previous
#include <cuda_runtime.h>
#include <cstdint>

// BatchDelayProcessor: lag-D feedback delay line.
//   c_k = x_k + FB * c_{k-1}         (carry per chain, c_{-1} = 0)
//   out_k = (1-MIX) * x_k + MIX * c_{k-1}
// Each (b, j) with j in [0, D) is an independent length-NBLK chain.
//
// R7: revert to the R3 structure (best: 39.36us). One change: output stores
// use st.global.wt (write-through). Theory: steady-state replay traffic is
// 226MB because dirty output lines evict the 113MB input from the 126MB L2.
// Write-through stores should leave no resident dirty lines -> x stays
// L2-resident across graph replays -> reads become L2 hits.

#define D_SAMP   22050
#define T_LEN    441000
#define B_SZ     64
#define NBLK     20          // T_LEN / D_SAMP
#define FB       0.3f
#define MIXC     0.5f

#define HD       (D_SAMP / 2)                 // 11025 float2 chains per batch row
#define NCHAINS  ((long long)B_SZ * HD)       // 705600

__device__ __forceinline__ float2 ld_x(const void* p) {
    float2 v;
    asm volatile("ld.global.nc.v2.f32 {%0,%1}, [%2];"
                 : "=f"(v.x), "=f"(v.y) : "l"(p));
    return v;
}

__device__ __forceinline__ void st_o(void* p, float2 v) {
    asm volatile("st.global.wt.v2.f32 [%0], {%1,%2};"
                 :: "l"(p), "f"(v.x), "f"(v.y) : "memory");
}

__global__ __launch_bounds__(256) void delay_kernel(const float* __restrict__ x,
                                                    float* __restrict__ out) {
    long long idx = (long long)blockIdx.x * blockDim.x + threadIdx.x;
    if (idx >= NCHAINS) return;

    int b = (int)(idx / HD);
    int j = (int)(idx % HD) * 2;

    const char* xbase = (const char*)(x + (size_t)b * T_LEN + j);
    char*       obase = (char*)(out + (size_t)b * T_LEN + j);

    const size_t blk_stride = (size_t)D_SAMP * sizeof(float);  // 88200 B

    // Front-batch all loads: independent addresses -> MLP = 20
    float2 xv[NBLK];
#pragma unroll
    for (int k = 0; k < NBLK; k++) {
        xv[k] = ld_x(xbase + (size_t)k * blk_stride);
    }

    float2 c;
    c.x = 0.0f;
    c.y = 0.0f;

#pragma unroll
    for (int k = 0; k < NBLK; k++) {
        float2 o;
        o.x = fmaf(c.x, MIXC, xv[k].x * (1.0f - MIXC));
        o.y = fmaf(c.y, MIXC, xv[k].y * (1.0f - MIXC));
        st_o(obase + (size_t)k * blk_stride, o);
        c.x = fmaf(c.x, FB, xv[k].x);
        c.y = fmaf(c.y, FB, xv[k].y);
    }
}

extern "C" void kernel_launch(void* const* d_in, const int* in_sizes, int n_in,
                              void* d_out, int out_size) {
    const float* x = (const float*)d_in[0];
    float* out = (float*)d_out;

    const int threads = 256;
    const long long nthreads = NCHAINS;
    const int blocks = (int)((nthreads + threads - 1) / threads);
    delay_kernel<<<blocks, threads>>>(x, out);
}